// round 9
// baseline (speedup 1.0000x reference)
#include <cuda_runtime.h>

#define BB 32
#define PP 196
#define NH 14

static __device__ unsigned int g_idx1[BB * PP * 64];
static __device__ float        g_out1[BB * PP * 256];
static __device__ unsigned int g_idx2[BB * PP * 64];
static __device__ float        g_out2[BB * PP * 256];
static __device__ unsigned int g_idx3[BB * PP * 16];

__device__ __forceinline__ void cp16(unsigned int dst, const void* src) {
    asm volatile("cp.async.cg.shared.global [%0], [%1], 16;\n" :: "r"(dst), "l"(src));
}
__device__ __forceinline__ void cpcommit() { asm volatile("cp.async.commit_group;\n" ::: "memory"); }
__device__ __forceinline__ void cpwait0()  { asm volatile("cp.async.wait_group 0;\n" ::: "memory"); }
__device__ __forceinline__ void cpwait1()  { asm volatile("cp.async.wait_group 1;\n" ::: "memory"); }

// ---------------- encode1: FMA dots, muladd c2 ----------------
__global__ void __launch_bounds__(256) k_encode1(const float* __restrict__ x,
                                                 const float* __restrict__ cent) {
    const int b = blockIdx.y, h = blockIdx.x, cb = threadIdx.x;
    float c[16][4], c2[16];
#pragma unroll
    for (int k = 0; k < 16; k++) {
#pragma unroll
        for (int j = 0; j < 4; j++) c[k][j] = cent[(cb * 16 + k) * 4 + j];
        float s = __fmul_rn(c[k][0], c[k][0]);
        s = __fadd_rn(s, __fmul_rn(c[k][1], c[k][1]));
        s = __fadd_rn(s, __fmul_rn(c[k][2], c[k][2]));
        s = __fadd_rn(s, __fmul_rn(c[k][3], c[k][3]));
        c2[k] = s;
    }
    for (int w = 0; w < NH; w++) {
        const int p = h * NH + w;
        const float v0 = x[(b * 1024 + cb * 4 + 0) * PP + p];
        const float v1 = x[(b * 1024 + cb * 4 + 1) * PP + p];
        const float v2 = x[(b * 1024 + cb * 4 + 2) * PP + p];
        const float v3 = x[(b * 1024 + cb * 4 + 3) * PP + p];
        float best = 3.4e38f; int bi = 0;
#pragma unroll
        for (int k = 0; k < 16; k++) {
            float d = __fmaf_rn(v0, c[k][0], 0.0f);
            d = __fmaf_rn(v1, c[k][1], d);
            d = __fmaf_rn(v2, c[k][2], d);
            d = __fmaf_rn(v3, c[k][3], d);
            const float s = __fadd_rn(c2[k], -__fmul_rn(2.0f, d));
            if (s < best) { best = s; bi = k; }
        }
        ((unsigned char*)g_idx1)[(b * PP + p) * 256 + cb] = (unsigned char)bi;
    }
}

// ---------------- encode2: FMA dots, muladd c2. smem 147456 ----------------
__global__ void __launch_bounds__(256) k_encode2(const float* __restrict__ cent) {
    extern __shared__ float sc[];
    const int b = blockIdx.y, h = blockIdx.x, c = threadIdx.x;
    for (int i = 0; i < 144; i++) sc[i * 256 + c] = cent[c * 144 + i];
    float c2[16];
#pragma unroll
    for (int k = 0; k < 16; k++) {
        float t0 = cent[c * 144 + k * 9];
        float s = __fmul_rn(t0, t0);
#pragma unroll
        for (int t = 1; t < 9; t++) {
            const float tv = cent[c * 144 + k * 9 + t];
            s = __fadd_rn(s, __fmul_rn(tv, tv));
        }
        c2[k] = s;
    }
    __syncthreads();
    for (int w = 0; w < NH; w++) {
        float v[9];
#pragma unroll
        for (int i = 0; i < 3; i++)
#pragma unroll
            for (int j = 0; j < 3; j++) {
                const int hh = h - 1 + i, ww = w - 1 + j;
                float val = 0.0f;
                if (hh >= 0 && hh < NH && ww >= 0 && ww < NH)
                    val = g_out1[(b * PP + hh * NH + ww) * 256 + c];
                v[i * 3 + j] = val;
            }
        float best = 3.4e38f; int bi = 0;
#pragma unroll
        for (int k = 0; k < 16; k++) {
            float d = __fmaf_rn(v[0], sc[(k * 9 + 0) * 256 + c], 0.0f);
#pragma unroll
            for (int t = 1; t < 9; t++) d = __fmaf_rn(v[t], sc[(k * 9 + t) * 256 + c], d);
            const float s = __fadd_rn(c2[k], -__fmul_rn(2.0f, d));
            if (s < best) { best = s; bi = k; }
        }
        ((unsigned char*)g_idx2)[(b * PP + h * NH + w) * 256 + c] = (unsigned char)bi;
    }
}

// ---------------- accum256: Eigen kc=248 blocked fold. smem 143616 ----------------
__device__ __forceinline__ void accum256_body(const unsigned int* __restrict__ gidx,
                                              const float* __restrict__ lut,
                                              const float* __restrict__ scale,
                                              const float* __restrict__ bias,
                                              float* __restrict__ out) {
    extern __shared__ float sm[];
    float* lutS = sm;
    unsigned int* idxS = (unsigned int*)(sm + 2 * 16384);
    const int b = blockIdx.y, q = blockIdx.x, o = threadIdx.x;
    const int p0 = q * 49;
    const unsigned int* gi = gidx + (b * PP + p0) * 64;
    for (int i = o; i < 49 * 64; i += 256) idxS[i] = gi[i];
    float acc[49], tot[49];
#pragma unroll
    for (int p = 0; p < 49; p++) { acc[p] = 0.0f; tot[p] = 0.0f; }
    const unsigned int sbase = (unsigned int)__cvta_generic_to_shared(lutS);
    const float4* gl = (const float4*)lut;
#pragma unroll
    for (int i = 0; i < 16; i++) cp16(sbase + (o + i * 256) * 16, (const void*)(gl + o + i * 256));
    cpcommit();
    int buf = 0;
    for (int ch = 0; ch < 64; ch++) {
        if (ch + 1 < 64) {
            const float4* s = gl + (ch + 1) * 4096;
            const unsigned int d0 = sbase + (unsigned int)(buf ^ 1) * 65536u;
#pragma unroll
            for (int i = 0; i < 16; i++) cp16(d0 + (o + i * 256) * 16, (const void*)(s + o + i * 256));
            cpcommit();
            cpwait1();
        } else {
            cpwait0();
        }
        __syncthreads();
        const float* L = lutS + buf * 16384;
        const unsigned int* iq = idxS + ch;
        // panel types for the 4 codebooks of this chunk (kc = 248)
        int fB[4], fC[4], Tt[4];
#pragma unroll
        for (int j = 0; j < 4; j++) {
            const int c = (ch << 2) + j, k16 = c << 4;
            const int r = k16 % 248;
            fB[j] = (r == 0 && c > 0) ? 1 : 0;
            const int pan0 = k16 / 248, pan1 = (k16 + 15) / 248;
            fC[j] = (!fB[j] && pan1 > pan0) ? 1 : 0;
            Tt[j] = pan1 * 248 - k16;
        }
#pragma unroll
        for (int p = 0; p < 49; p++) {
            const unsigned int wv = iq[p * 64];
            float a = acc[p], tt = tot[p];
#pragma unroll
            for (int j = 0; j < 4; j++) {
                const unsigned int idx = (wv >> (8 * j)) & 255u;
                const float t = L[((j << 4) + idx) * 256 + o];
                const bool foldB = fB[j] || (fC[j] && (int)idx >= Tt[j]);
                if (foldB) { tt = __fadd_rn(tt, a); a = t; }
                else {
                    a = __fadd_rn(a, t);
                    if (fC[j]) { tt = __fadd_rn(tt, a); a = 0.0f; }
                }
            }
            acc[p] = a; tot[p] = tt;
        }
        __syncthreads();
        buf ^= 1;
    }
    const float scv = scale[o], biv = bias[o];
    for (int p = 0; p < 49; p++) {
        const float s = __fadd_rn(tot[p], acc[p]);          // fold last panel
        float t = __fadd_rn(__fmul_rn(s, scv), biv);        // BN mul+add
        t = fmaxf(t, 0.0f);
        out[(b * PP + p0 + p) * 256 + o] = t;
    }
}

__global__ void __launch_bounds__(256, 1) k_accum_l1(const float* __restrict__ lut,
                                                     const float* __restrict__ scale,
                                                     const float* __restrict__ bias) {
    accum256_body(g_idx1, lut, scale, bias, g_out1);
}
__global__ void __launch_bounds__(256, 1) k_accum_l2(const float* __restrict__ lut,
                                                     const float* __restrict__ scale,
                                                     const float* __restrict__ bias) {
    accum256_body(g_idx2, lut, scale, bias, g_out2);
}

// ---------------- encode3: FMA dots, muladd c2 ----------------
__global__ void __launch_bounds__(64) k_encode3(const float* __restrict__ cent) {
    const int b = blockIdx.y, h = blockIdx.x, cb = threadIdx.x;
    float c[16][4], c2[16];
#pragma unroll
    for (int k = 0; k < 16; k++) {
#pragma unroll
        for (int j = 0; j < 4; j++) c[k][j] = cent[(cb * 16 + k) * 4 + j];
        float s = __fmul_rn(c[k][0], c[k][0]);
        s = __fadd_rn(s, __fmul_rn(c[k][1], c[k][1]));
        s = __fadd_rn(s, __fmul_rn(c[k][2], c[k][2]));
        s = __fadd_rn(s, __fmul_rn(c[k][3], c[k][3]));
        c2[k] = s;
    }
    for (int w = 0; w < NH; w++) {
        const int p = h * NH + w;
        const float4 v = *(const float4*)&g_out2[(b * PP + p) * 256 + cb * 4];
        float best = 3.4e38f; int bi = 0;
#pragma unroll
        for (int k = 0; k < 16; k++) {
            float d = __fmaf_rn(v.x, c[k][0], 0.0f);
            d = __fmaf_rn(v.y, c[k][1], d);
            d = __fmaf_rn(v.z, c[k][2], d);
            d = __fmaf_rn(v.w, c[k][3], d);
            const float s = __fadd_rn(c2[k], -__fmul_rn(2.0f, d));
            if (s < best) { best = s; bi = k; }
        }
        ((unsigned char*)g_idx3)[(b * PP + p) * 64 + cb] = (unsigned char)bi;
    }
}

// ---------------- accum3: flat sum (order irrelevant downstream). smem 132864 ----------------
__global__ void __launch_bounds__(256, 1) k_accum3(const float* __restrict__ lut,
                                                   const float* __restrict__ scale,
                                                   const float* __restrict__ bias,
                                                   const float* __restrict__ xin,
                                                   float* __restrict__ out) {
    extern __shared__ float sm[];
    float* lutS = sm;
    unsigned char* idxS = (unsigned char*)(sm + 2 * 16384);
    const int b = blockIdx.y, g = blockIdx.x, t = threadIdx.x;
    const int p0 = g * 28;
    const unsigned int* gi = (const unsigned int*)((const unsigned char*)g_idx3 + (b * PP + p0) * 64);
    for (int i = t; i < 28 * 16; i += 256) ((unsigned int*)idxS)[i] = gi[i];
    float4 acc[28];
#pragma unroll
    for (int p = 0; p < 28; p++) acc[p] = make_float4(0.f, 0.f, 0.f, 0.f);
    const unsigned int sbase = (unsigned int)__cvta_generic_to_shared(lutS);
    const float4* gl = (const float4*)lut;
#pragma unroll
    for (int i = 0; i < 16; i++) cp16(sbase + (t + i * 256) * 16, (const void*)(gl + t + i * 256));
    cpcommit();
    int buf = 0;
    for (int cb = 0; cb < 64; cb++) {
        if (cb + 1 < 64) {
            const float4* s = gl + (cb + 1) * 4096;
            const unsigned int d0 = sbase + (unsigned int)(buf ^ 1) * 65536u;
#pragma unroll
            for (int i = 0; i < 16; i++) cp16(d0 + (t + i * 256) * 16, (const void*)(s + t + i * 256));
            cpcommit();
            cpwait1();
        } else {
            cpwait0();
        }
        __syncthreads();
        const float* L = lutS + buf * 16384;
#pragma unroll
        for (int p = 0; p < 28; p++) {
            const unsigned int k = idxS[p * 64 + cb];
            const float4 lv = *(const float4*)(L + k * 1024 + t * 4);
            acc[p].x = __fadd_rn(acc[p].x, lv.x);
            acc[p].y = __fadd_rn(acc[p].y, lv.y);
            acc[p].z = __fadd_rn(acc[p].z, lv.z);
            acc[p].w = __fadd_rn(acc[p].w, lv.w);
        }
        __syncthreads();
        buf ^= 1;
    }
    const float s0 = scale[t * 4 + 0], s1 = scale[t * 4 + 1], s2 = scale[t * 4 + 2], s3 = scale[t * 4 + 3];
    const float b0 = bias[t * 4 + 0], b1 = bias[t * 4 + 1], b2 = bias[t * 4 + 2], b3 = bias[t * 4 + 3];
    for (int p = 0; p < 28; p++) {
        const int pg = p0 + p;
        float r;
        r = __fadd_rn(__fadd_rn(__fmul_rn(acc[p].x, s0), b0), xin[(b * 1024 + t * 4 + 0) * PP + pg]);
        out[(b * 1024 + t * 4 + 0) * PP + pg] = fmaxf(r, 0.0f);
        r = __fadd_rn(__fadd_rn(__fmul_rn(acc[p].y, s1), b1), xin[(b * 1024 + t * 4 + 1) * PP + pg]);
        out[(b * 1024 + t * 4 + 1) * PP + pg] = fmaxf(r, 0.0f);
        r = __fadd_rn(__fadd_rn(__fmul_rn(acc[p].z, s2), b2), xin[(b * 1024 + t * 4 + 2) * PP + pg]);
        out[(b * 1024 + t * 4 + 2) * PP + pg] = fmaxf(r, 0.0f);
        r = __fadd_rn(__fadd_rn(__fmul_rn(acc[p].w, s3), b3), xin[(b * 1024 + t * 4 + 3) * PP + pg]);
        out[(b * 1024 + t * 4 + 3) * PP + pg] = fmaxf(r, 0.0f);
    }
}

extern "C" void kernel_launch(void* const* d_in, const int* in_sizes, int n_in,
                              void* d_out, int out_size) {
    const float* x   = (const float*)d_in[0];
    const float* c1c = (const float*)d_in[1];
    const float* c1l = (const float*)d_in[2];
    const float* c1s = (const float*)d_in[3];
    const float* c1b = (const float*)d_in[4];
    const float* c2c = (const float*)d_in[5];
    const float* c2l = (const float*)d_in[6];
    const float* c2s = (const float*)d_in[7];
    const float* c2b = (const float*)d_in[8];
    const float* c3c = (const float*)d_in[9];
    const float* c3l = (const float*)d_in[10];
    const float* c3s = (const float*)d_in[11];
    const float* c3b = (const float*)d_in[12];
    float* out = (float*)d_out;

    cudaFuncSetAttribute(k_encode2,  cudaFuncAttributeMaxDynamicSharedMemorySize, 147456);
    cudaFuncSetAttribute(k_accum_l1, cudaFuncAttributeMaxDynamicSharedMemorySize, 143616);
    cudaFuncSetAttribute(k_accum_l2, cudaFuncAttributeMaxDynamicSharedMemorySize, 143616);
    cudaFuncSetAttribute(k_accum3,   cudaFuncAttributeMaxDynamicSharedMemorySize, 132864);

    k_encode1<<<dim3(NH, BB), 256>>>(x, c1c);
    k_accum_l1<<<dim3(4, BB), 256, 143616>>>(c1l, c1s, c1b);
    k_encode2<<<dim3(NH, BB), 256, 147456>>>(c2c);
    k_accum_l2<<<dim3(4, BB), 256, 143616>>>(c2l, c2s, c2b);
    k_encode3<<<dim3(NH, BB), 64>>>(c3c);
    k_accum3<<<dim3(7, BB), 256, 132864>>>(c3l, c3s, c3b, x, out);
    (void)in_sizes; (void)n_in; (void)out_size;
}

// round 10
// speedup vs baseline: 1.7635x; 1.7635x over previous
#include <cuda_runtime.h>

#define BB 32
#define PP 196
#define NH 14

static __device__ unsigned int g_idx1[BB * PP * 64];
static __device__ float        g_out1[BB * PP * 256];
static __device__ unsigned int g_idx2[BB * PP * 64];
static __device__ float        g_out2[BB * PP * 256];
static __device__ unsigned int g_idx3[BB * PP * 16];

__device__ __forceinline__ void cp16(unsigned int dst, const void* src) {
    asm volatile("cp.async.cg.shared.global [%0], [%1], 16;\n" :: "r"(dst), "l"(src));
}
__device__ __forceinline__ void cpcommit() { asm volatile("cp.async.commit_group;\n" ::: "memory"); }
__device__ __forceinline__ void cpwait0()  { asm volatile("cp.async.wait_group 0;\n" ::: "memory"); }
__device__ __forceinline__ void cpwait1()  { asm volatile("cp.async.wait_group 1;\n" ::: "memory"); }

// ---------------- encode1: FMA dots, muladd c2 (R9, passing) ----------------
__global__ void __launch_bounds__(256) k_encode1(const float* __restrict__ x,
                                                 const float* __restrict__ cent) {
    const int b = blockIdx.y, h = blockIdx.x, cb = threadIdx.x;
    float c[16][4], c2[16];
#pragma unroll
    for (int k = 0; k < 16; k++) {
#pragma unroll
        for (int j = 0; j < 4; j++) c[k][j] = cent[(cb * 16 + k) * 4 + j];
        float s = __fmul_rn(c[k][0], c[k][0]);
        s = __fadd_rn(s, __fmul_rn(c[k][1], c[k][1]));
        s = __fadd_rn(s, __fmul_rn(c[k][2], c[k][2]));
        s = __fadd_rn(s, __fmul_rn(c[k][3], c[k][3]));
        c2[k] = s;
    }
    for (int w = 0; w < NH; w++) {
        const int p = h * NH + w;
        const float v0 = x[(b * 1024 + cb * 4 + 0) * PP + p];
        const float v1 = x[(b * 1024 + cb * 4 + 1) * PP + p];
        const float v2 = x[(b * 1024 + cb * 4 + 2) * PP + p];
        const float v3 = x[(b * 1024 + cb * 4 + 3) * PP + p];
        float best = 3.4e38f; int bi = 0;
#pragma unroll
        for (int k = 0; k < 16; k++) {
            float d = __fmaf_rn(v0, c[k][0], 0.0f);
            d = __fmaf_rn(v1, c[k][1], d);
            d = __fmaf_rn(v2, c[k][2], d);
            d = __fmaf_rn(v3, c[k][3], d);
            const float s = __fadd_rn(c2[k], -__fmul_rn(2.0f, d));
            if (s < best) { best = s; bi = k; }
        }
        ((unsigned char*)g_idx1)[(b * PP + p) * 256 + cb] = (unsigned char)bi;
    }
}

// ---------------- encode2 (R9, passing). smem 147456 ----------------
__global__ void __launch_bounds__(256) k_encode2(const float* __restrict__ cent) {
    extern __shared__ float sc[];
    const int b = blockIdx.y, h = blockIdx.x, c = threadIdx.x;
    for (int i = 0; i < 144; i++) sc[i * 256 + c] = cent[c * 144 + i];
    float c2[16];
#pragma unroll
    for (int k = 0; k < 16; k++) {
        float t0 = cent[c * 144 + k * 9];
        float s = __fmul_rn(t0, t0);
#pragma unroll
        for (int t = 1; t < 9; t++) {
            const float tv = cent[c * 144 + k * 9 + t];
            s = __fadd_rn(s, __fmul_rn(tv, tv));
        }
        c2[k] = s;
    }
    __syncthreads();
    for (int w = 0; w < NH; w++) {
        float v[9];
#pragma unroll
        for (int i = 0; i < 3; i++)
#pragma unroll
            for (int j = 0; j < 3; j++) {
                const int hh = h - 1 + i, ww = w - 1 + j;
                float val = 0.0f;
                if (hh >= 0 && hh < NH && ww >= 0 && ww < NH)
                    val = g_out1[(b * PP + hh * NH + ww) * 256 + c];
                v[i * 3 + j] = val;
            }
        float best = 3.4e38f; int bi = 0;
#pragma unroll
        for (int k = 0; k < 16; k++) {
            float d = __fmaf_rn(v[0], sc[(k * 9 + 0) * 256 + c], 0.0f);
#pragma unroll
            for (int t = 1; t < 9; t++) d = __fmaf_rn(v[t], sc[(k * 9 + t) * 256 + c], d);
            const float s = __fadd_rn(c2[k], -__fmul_rn(2.0f, d));
            if (s < best) { best = s; bi = k; }
        }
        ((unsigned char*)g_idx2)[(b * PP + h * NH + w) * 256 + c] = (unsigned char)bi;
    }
}

// ===================================================================
// accum12: layers 1&2 LUT accumulate with Eigen kc=248 blocked fold.
// float4 over outputs: 256 threads = 64 o-groups x 4 pos-subsets.
// Thread (og, ps): outputs og*4..+3, positions p = ps + 4*i.
// grid (4, 32). dyn smem = 2*65536 + 49*64*4 = 143616.
// ===================================================================
__device__ __forceinline__ void accum12_body(const unsigned int* __restrict__ gidx,
                                             const float* __restrict__ lut,
                                             const float* __restrict__ scale,
                                             const float* __restrict__ bias,
                                             float* __restrict__ out) {
    extern __shared__ float sm[];
    float* lutS = sm;                                       // 2 * 16384 floats
    unsigned int* idxS = (unsigned int*)(sm + 2 * 16384);   // 49*64 words
    const int b = blockIdx.y, q = blockIdx.x, t = threadIdx.x;
    const int og = t & 63, ps = t >> 6;
    const int p0 = q * 49;
    const unsigned int* gi = gidx + (b * PP + p0) * 64;
    for (int i = t; i < 49 * 64; i += 256) idxS[i] = gi[i];
    const int NI = (ps == 0) ? 13 : 12;
    float4 acc[13], tot[13];
#pragma unroll
    for (int i = 0; i < 13; i++) {
        acc[i] = make_float4(0.f, 0.f, 0.f, 0.f);
        tot[i] = make_float4(0.f, 0.f, 0.f, 0.f);
    }
    const unsigned int sbase = (unsigned int)__cvta_generic_to_shared(lutS);
    const float4* gl = (const float4*)lut;
#pragma unroll
    for (int i = 0; i < 16; i++) cp16(sbase + (t + i * 256) * 16, (const void*)(gl + t + i * 256));
    cpcommit();
    int buf = 0;
    for (int ch = 0; ch < 64; ch++) {
        if (ch + 1 < 64) {
            const float4* s = gl + (ch + 1) * 4096;
            const unsigned int d0 = sbase + (unsigned int)(buf ^ 1) * 65536u;
#pragma unroll
            for (int i = 0; i < 16; i++) cp16(d0 + (t + i * 256) * 16, (const void*)(s + t + i * 256));
            cpcommit();
            cpwait1();
        } else {
            cpwait0();
        }
        __syncthreads();
        const float* L = lutS + buf * 16384;
        // kc=248 panel flags for the 4 codebooks of this chunk
        int fB[4], fC[4], Tt[4], any = 0;
#pragma unroll
        for (int j = 0; j < 4; j++) {
            const int c = (ch << 2) + j, k16 = c << 4;
            fB[j] = ((k16 % 248) == 0 && c > 0) ? 1 : 0;
            const int pan0 = k16 / 248, pan1 = (k16 + 15) / 248;
            fC[j] = (!fB[j] && pan1 > pan0) ? 1 : 0;
            Tt[j] = pan1 * 248 - k16;
            any |= fB[j] | fC[j];
        }
        if (!any) {
            // fast path: no panel boundary in this chunk
#pragma unroll
            for (int i = 0; i < 13; i++) {
                if (i < NI) {
                    const int p = ps + 4 * i;
                    const unsigned int wv = idxS[p * 64 + ch];
#pragma unroll
                    for (int j = 0; j < 4; j++) {
                        const unsigned int idx = (wv >> (8 * j)) & 255u;
                        const float4 lv = *(const float4*)(L + (((j << 4) + idx) << 8) + (og << 2));
                        acc[i].x = __fadd_rn(acc[i].x, lv.x);
                        acc[i].y = __fadd_rn(acc[i].y, lv.y);
                        acc[i].z = __fadd_rn(acc[i].z, lv.z);
                        acc[i].w = __fadd_rn(acc[i].w, lv.w);
                    }
                }
            }
        } else {
#pragma unroll
            for (int i = 0; i < 13; i++) {
                if (i < NI) {
                    const int p = ps + 4 * i;
                    const unsigned int wv = idxS[p * 64 + ch];
#pragma unroll
                    for (int j = 0; j < 4; j++) {
                        const unsigned int idx = (wv >> (8 * j)) & 255u;
                        const float4 lv = *(const float4*)(L + (((j << 4) + idx) << 8) + (og << 2));
                        const bool foldB = fB[j] || (fC[j] && (int)idx >= Tt[j]);
                        if (foldB) {
                            tot[i].x = __fadd_rn(tot[i].x, acc[i].x); acc[i].x = lv.x;
                            tot[i].y = __fadd_rn(tot[i].y, acc[i].y); acc[i].y = lv.y;
                            tot[i].z = __fadd_rn(tot[i].z, acc[i].z); acc[i].z = lv.z;
                            tot[i].w = __fadd_rn(tot[i].w, acc[i].w); acc[i].w = lv.w;
                        } else {
                            acc[i].x = __fadd_rn(acc[i].x, lv.x);
                            acc[i].y = __fadd_rn(acc[i].y, lv.y);
                            acc[i].z = __fadd_rn(acc[i].z, lv.z);
                            acc[i].w = __fadd_rn(acc[i].w, lv.w);
                            if (fC[j]) {
                                tot[i].x = __fadd_rn(tot[i].x, acc[i].x); acc[i].x = 0.f;
                                tot[i].y = __fadd_rn(tot[i].y, acc[i].y); acc[i].y = 0.f;
                                tot[i].z = __fadd_rn(tot[i].z, acc[i].z); acc[i].z = 0.f;
                                tot[i].w = __fadd_rn(tot[i].w, acc[i].w); acc[i].w = 0.f;
                            }
                        }
                    }
                }
            }
        }
        __syncthreads();
        buf ^= 1;
    }
    const float4 sc4 = ((const float4*)scale)[og];
    const float4 bi4 = ((const float4*)bias)[og];
#pragma unroll
    for (int i = 0; i < 13; i++) {
        if (i < NI) {
            const int p = p0 + ps + 4 * i;
            float4 r;
            float s;
            s = __fadd_rn(tot[i].x, acc[i].x);
            r.x = fmaxf(__fadd_rn(__fmul_rn(s, sc4.x), bi4.x), 0.0f);
            s = __fadd_rn(tot[i].y, acc[i].y);
            r.y = fmaxf(__fadd_rn(__fmul_rn(s, sc4.y), bi4.y), 0.0f);
            s = __fadd_rn(tot[i].z, acc[i].z);
            r.z = fmaxf(__fadd_rn(__fmul_rn(s, sc4.z), bi4.z), 0.0f);
            s = __fadd_rn(tot[i].w, acc[i].w);
            r.w = fmaxf(__fadd_rn(__fmul_rn(s, sc4.w), bi4.w), 0.0f);
            *(float4*)(out + (b * PP + p) * 256 + (og << 2)) = r;
        }
    }
}

__global__ void __launch_bounds__(256, 1) k_accum_l1(const float* __restrict__ lut,
                                                     const float* __restrict__ scale,
                                                     const float* __restrict__ bias) {
    accum12_body(g_idx1, lut, scale, bias, g_out1);
}
__global__ void __launch_bounds__(256, 1) k_accum_l2(const float* __restrict__ lut,
                                                     const float* __restrict__ scale,
                                                     const float* __restrict__ bias) {
    accum12_body(g_idx2, lut, scale, bias, g_out2);
}

// ---------------- encode3 (R9, passing) ----------------
__global__ void __launch_bounds__(64) k_encode3(const float* __restrict__ cent) {
    const int b = blockIdx.y, h = blockIdx.x, cb = threadIdx.x;
    float c[16][4], c2[16];
#pragma unroll
    for (int k = 0; k < 16; k++) {
#pragma unroll
        for (int j = 0; j < 4; j++) c[k][j] = cent[(cb * 16 + k) * 4 + j];
        float s = __fmul_rn(c[k][0], c[k][0]);
        s = __fadd_rn(s, __fmul_rn(c[k][1], c[k][1]));
        s = __fadd_rn(s, __fmul_rn(c[k][2], c[k][2]));
        s = __fadd_rn(s, __fmul_rn(c[k][3], c[k][3]));
        c2[k] = s;
    }
    for (int w = 0; w < NH; w++) {
        const int p = h * NH + w;
        const float4 v = *(const float4*)&g_out2[(b * PP + p) * 256 + cb * 4];
        float best = 3.4e38f; int bi = 0;
#pragma unroll
        for (int k = 0; k < 16; k++) {
            float d = __fmaf_rn(v.x, c[k][0], 0.0f);
            d = __fmaf_rn(v.y, c[k][1], d);
            d = __fmaf_rn(v.z, c[k][2], d);
            d = __fmaf_rn(v.w, c[k][3], d);
            const float s = __fadd_rn(c2[k], -__fmul_rn(2.0f, d));
            if (s < best) { best = s; bi = k; }
        }
        ((unsigned char*)g_idx3)[(b * PP + p) * 64 + cb] = (unsigned char)bi;
    }
}

// ===================================================================
// accum3: 64 codebooks -> 1024 outputs (flat sequential sum), BN +
// residual + relu. Block = 49 pos x 512-output half.
// grid (8, 32): gx -> pg = gx&3 (pos group), oh = gx>>2 (o-half).
// 256 threads = 128 o-groups x 2 pos-subsets. Chunk = 2 cb (64 KB), dbuf.
// Epilogue transposes via smem for coalesced CHW stores + residual reads.
// dyn smem = 2*65536 + 49*64 = 134208.
// ===================================================================
__global__ void __launch_bounds__(256, 1) k_accum3(const float* __restrict__ lut,
                                                   const float* __restrict__ scale,
                                                   const float* __restrict__ bias,
                                                   const float* __restrict__ xin,
                                                   float* __restrict__ out) {
    extern __shared__ float sm[];
    float* lutS = sm;                                        // 2 * 16384 floats
    unsigned char* idxB = (unsigned char*)(sm + 2 * 16384);  // 49*64 bytes
    const int b = blockIdx.y, gx = blockIdx.x, t = threadIdx.x;
    const int pg = gx & 3, oh = gx >> 2;
    const int og = t & 127, ps = t >> 7;
    const int p0 = pg * 49;
    const unsigned int* gi = (const unsigned int*)((const unsigned char*)g_idx3 + (b * PP + p0) * 64);
    for (int i = t; i < 49 * 16; i += 256) ((unsigned int*)idxB)[i] = gi[i];
    const int NI = (ps == 0) ? 25 : 24;
    float4 acc[25];
#pragma unroll
    for (int i = 0; i < 25; i++) acc[i] = make_float4(0.f, 0.f, 0.f, 0.f);
    const unsigned int sbase = (unsigned int)__cvta_generic_to_shared(lutS);
    const float4* gl = (const float4*)lut;
    // chunk c2 covers cb {2*c2, 2*c2+1}: 32 rows x 512 floats (o-half slice)
#pragma unroll
    for (int i = 0; i < 16; i++) {
        const int e4 = i * 256 + t;
        const int row = e4 >> 7, c4 = e4 & 127;
        cp16(sbase + e4 * 16, (const void*)(gl + row * 256 + oh * 128 + c4));
    }
    cpcommit();
    int buf = 0;
    for (int c2 = 0; c2 < 32; c2++) {
        if (c2 + 1 < 32) {
            const unsigned int d0 = sbase + (unsigned int)(buf ^ 1) * 65536u;
#pragma unroll
            for (int i = 0; i < 16; i++) {
                const int e4 = i * 256 + t;
                const int row = e4 >> 7, c4 = e4 & 127;
                cp16(d0 + e4 * 16, (const void*)(gl + ((c2 + 1) * 32 + row) * 256 + oh * 128 + c4));
            }
            cpcommit();
            cpwait1();
        } else {
            cpwait0();
        }
        __syncthreads();
        const float* L = lutS + buf * 16384;
#pragma unroll
        for (int i = 0; i < 25; i++) {
            if (i < NI) {
                const int p = ps + 2 * i;
                const unsigned char* ib = idxB + p * 64 + (c2 << 1);
#pragma unroll
                for (int j = 0; j < 2; j++) {
                    const unsigned int idx = ib[j];
                    const float4 lv = *(const float4*)(L + (((j << 4) + idx) << 9) + (og << 2));
                    acc[i].x = __fadd_rn(acc[i].x, lv.x);
                    acc[i].y = __fadd_rn(acc[i].y, lv.y);
                    acc[i].z = __fadd_rn(acc[i].z, lv.z);
                    acc[i].w = __fadd_rn(acc[i].w, lv.w);
                }
            }
        }
        __syncthreads();
        buf ^= 1;
    }
    // transpose via smem: tr[o_local][p], stride 49
    float* tr = lutS;   // 512*49 floats = 100352 B <= 131072 B
    __syncthreads();
#pragma unroll
    for (int i = 0; i < 25; i++) {
        if (i < NI) {
            const int p = ps + 2 * i;
            tr[(og * 4 + 0) * 49 + p] = acc[i].x;
            tr[(og * 4 + 1) * 49 + p] = acc[i].y;
            tr[(og * 4 + 2) * 49 + p] = acc[i].z;
            tr[(og * 4 + 3) * 49 + p] = acc[i].w;
        }
    }
    __syncthreads();
    for (int ol = t; ol < 512; ol += 256) {
        const int O = oh * 512 + ol;
        const float scv = scale[O], biv = bias[O];
        const int base = (b * 1024 + O) * PP + p0;
        const float* trr = tr + ol * 49;
        for (int p = 0; p < 49; p++) {
            float r = __fadd_rn(__fadd_rn(__fmul_rn(trr[p], scv), biv), xin[base + p]);
            out[base + p] = fmaxf(r, 0.0f);
        }
    }
}

extern "C" void kernel_launch(void* const* d_in, const int* in_sizes, int n_in,
                              void* d_out, int out_size) {
    const float* x   = (const float*)d_in[0];
    const float* c1c = (const float*)d_in[1];
    const float* c1l = (const float*)d_in[2];
    const float* c1s = (const float*)d_in[3];
    const float* c1b = (const float*)d_in[4];
    const float* c2c = (const float*)d_in[5];
    const float* c2l = (const float*)d_in[6];
    const float* c2s = (const float*)d_in[7];
    const float* c2b = (const float*)d_in[8];
    const float* c3c = (const float*)d_in[9];
    const float* c3l = (const float*)d_in[10];
    const float* c3s = (const float*)d_in[11];
    const float* c3b = (const float*)d_in[12];
    float* out = (float*)d_out;

    cudaFuncSetAttribute(k_encode2,  cudaFuncAttributeMaxDynamicSharedMemorySize, 147456);
    cudaFuncSetAttribute(k_accum_l1, cudaFuncAttributeMaxDynamicSharedMemorySize, 143616);
    cudaFuncSetAttribute(k_accum_l2, cudaFuncAttributeMaxDynamicSharedMemorySize, 143616);
    cudaFuncSetAttribute(k_accum3,   cudaFuncAttributeMaxDynamicSharedMemorySize, 134208);

    k_encode1<<<dim3(NH, BB), 256>>>(x, c1c);
    k_accum_l1<<<dim3(4, BB), 256, 143616>>>(c1l, c1s, c1b);
    k_encode2<<<dim3(NH, BB), 256, 147456>>>(c2c);
    k_accum_l2<<<dim3(4, BB), 256, 143616>>>(c2l, c2s, c2b);
    k_encode3<<<dim3(NH, BB), 64>>>(c3c);
    k_accum3<<<dim3(8, BB), 256, 134208>>>(c3l, c3s, c3b, x, out);
    (void)in_sizes; (void)n_in; (void)out_size;
}

// round 11
// speedup vs baseline: 1.8016x; 1.0216x over previous
#include <cuda_runtime.h>

#define BB 32
#define PP 196
#define NH 14

static __device__ unsigned int g_idx1[BB * PP * 64];
static __device__ float        g_out1[BB * PP * 256];
static __device__ unsigned int g_idx2[BB * PP * 64];
static __device__ float        g_out2[BB * PP * 256];
static __device__ unsigned int g_idx3[BB * PP * 16];

__device__ __forceinline__ void cp16(unsigned int dst, const void* src) {
    asm volatile("cp.async.cg.shared.global [%0], [%1], 16;\n" :: "r"(dst), "l"(src));
}
__device__ __forceinline__ void cpcommit() { asm volatile("cp.async.commit_group;\n" ::: "memory"); }
__device__ __forceinline__ void cpwait0()  { asm volatile("cp.async.wait_group 0;\n" ::: "memory"); }
__device__ __forceinline__ void cpwait1()  { asm volatile("cp.async.wait_group 1;\n" ::: "memory"); }

// ---------------- encode1: smem-staged x tile, FMA dots. dyn smem 57344 ----------------
__global__ void __launch_bounds__(256) k_encode1(const float* __restrict__ x,
                                                 const float* __restrict__ cent) {
    extern __shared__ float xs[];   // [c][w]: 1024*14 floats
    const int b = blockIdx.y, h = blockIdx.x, cb = threadIdx.x;
    for (int i = cb; i < 1024 * 14; i += 256) {
        const int c = i / 14, w = i % 14;
        xs[i] = x[(b * 1024 + c) * PP + h * NH + w];
    }
    float c[16][4], c2[16];
#pragma unroll
    for (int k = 0; k < 16; k++) {
#pragma unroll
        for (int j = 0; j < 4; j++) c[k][j] = cent[(cb * 16 + k) * 4 + j];
        float s = __fmul_rn(c[k][0], c[k][0]);
        s = __fadd_rn(s, __fmul_rn(c[k][1], c[k][1]));
        s = __fadd_rn(s, __fmul_rn(c[k][2], c[k][2]));
        s = __fadd_rn(s, __fmul_rn(c[k][3], c[k][3]));
        c2[k] = s;
    }
    __syncthreads();
    for (int w = 0; w < NH; w++) {
        const float v0 = xs[(cb * 4 + 0) * 14 + w];
        const float v1 = xs[(cb * 4 + 1) * 14 + w];
        const float v2 = xs[(cb * 4 + 2) * 14 + w];
        const float v3 = xs[(cb * 4 + 3) * 14 + w];
        float best = 3.4e38f; int bi = 0;
#pragma unroll
        for (int k = 0; k < 16; k++) {
            float d = __fmaf_rn(v0, c[k][0], 0.0f);
            d = __fmaf_rn(v1, c[k][1], d);
            d = __fmaf_rn(v2, c[k][2], d);
            d = __fmaf_rn(v3, c[k][3], d);
            const float s = __fadd_rn(c2[k], -__fmul_rn(2.0f, d));
            if (s < best) { best = s; bi = k; }
        }
        ((unsigned char*)g_idx1)[(b * PP + h * NH + w) * 256 + cb] = (unsigned char)bi;
    }
}

// ---------------- encode2 (unchanged, passing). smem 147456 ----------------
__global__ void __launch_bounds__(256) k_encode2(const float* __restrict__ cent) {
    extern __shared__ float sc[];
    const int b = blockIdx.y, h = blockIdx.x, c = threadIdx.x;
    for (int i = 0; i < 144; i++) sc[i * 256 + c] = cent[c * 144 + i];
    float c2[16];
#pragma unroll
    for (int k = 0; k < 16; k++) {
        float t0 = cent[c * 144 + k * 9];
        float s = __fmul_rn(t0, t0);
#pragma unroll
        for (int t = 1; t < 9; t++) {
            const float tv = cent[c * 144 + k * 9 + t];
            s = __fadd_rn(s, __fmul_rn(tv, tv));
        }
        c2[k] = s;
    }
    __syncthreads();
    for (int w = 0; w < NH; w++) {
        float v[9];
#pragma unroll
        for (int i = 0; i < 3; i++)
#pragma unroll
            for (int j = 0; j < 3; j++) {
                const int hh = h - 1 + i, ww = w - 1 + j;
                float val = 0.0f;
                if (hh >= 0 && hh < NH && ww >= 0 && ww < NH)
                    val = g_out1[(b * PP + hh * NH + ww) * 256 + c];
                v[i * 3 + j] = val;
            }
        float best = 3.4e38f; int bi = 0;
#pragma unroll
        for (int k = 0; k < 16; k++) {
            float d = __fmaf_rn(v[0], sc[(k * 9 + 0) * 256 + c], 0.0f);
#pragma unroll
            for (int t = 1; t < 9; t++) d = __fmaf_rn(v[t], sc[(k * 9 + t) * 256 + c], d);
            const float s = __fadd_rn(c2[k], -__fmul_rn(2.0f, d));
            if (s < best) { best = s; bi = k; }
        }
        ((unsigned char*)g_idx2)[(b * PP + h * NH + w) * 256 + c] = (unsigned char)bi;
    }
}

// ===================================================================
// accum12: kc=248 blocked fold, 512 threads = 64 og x 8 ps.
// Thread (og, ps): outputs og*4..+3, positions p = ps + 8*i.
// grid (4, 32). dyn smem = 2*65536 + 49*64*4 = 143616.
// ===================================================================
__device__ __forceinline__ void accum12_body(const unsigned int* __restrict__ gidx,
                                             const float* __restrict__ lut,
                                             const float* __restrict__ scale,
                                             const float* __restrict__ bias,
                                             float* __restrict__ out) {
    extern __shared__ float sm[];
    float* lutS = sm;
    unsigned int* idxS = (unsigned int*)(sm + 2 * 16384);
    const int b = blockIdx.y, q = blockIdx.x, t = threadIdx.x;
    const int og = t & 63, ps = t >> 6;
    const int p0 = q * 49;
    const unsigned int* gi = gidx + (b * PP + p0) * 64;
    for (int i = t; i < 49 * 64; i += 512) idxS[i] = gi[i];
    const int NI = (ps == 0) ? 7 : ((48 - ps) / 8 + 1);
    float4 acc[7], tot[7];
#pragma unroll
    for (int i = 0; i < 7; i++) {
        acc[i] = make_float4(0.f, 0.f, 0.f, 0.f);
        tot[i] = make_float4(0.f, 0.f, 0.f, 0.f);
    }
    const unsigned int sbase = (unsigned int)__cvta_generic_to_shared(lutS);
    const float4* gl = (const float4*)lut;
#pragma unroll
    for (int i = 0; i < 8; i++) cp16(sbase + (t + i * 512) * 16, (const void*)(gl + t + i * 512));
    cpcommit();
    int buf = 0;
    for (int ch = 0; ch < 64; ch++) {
        if (ch + 1 < 64) {
            const float4* s = gl + (ch + 1) * 4096;
            const unsigned int d0 = sbase + (unsigned int)(buf ^ 1) * 65536u;
#pragma unroll
            for (int i = 0; i < 8; i++) cp16(d0 + (t + i * 512) * 16, (const void*)(s + t + i * 512));
            cpcommit();
            cpwait1();
        } else {
            cpwait0();
        }
        __syncthreads();
        const float* L = lutS + buf * 16384;
        int fB[4], fC[4], Tt[4], any = 0;
#pragma unroll
        for (int j = 0; j < 4; j++) {
            const int c = (ch << 2) + j, k16 = c << 4;
            fB[j] = ((k16 % 248) == 0 && c > 0) ? 1 : 0;
            const int pan0 = k16 / 248, pan1 = (k16 + 15) / 248;
            fC[j] = (!fB[j] && pan1 > pan0) ? 1 : 0;
            Tt[j] = pan1 * 248 - k16;
            any |= fB[j] | fC[j];
        }
        if (!any) {
#pragma unroll
            for (int i = 0; i < 7; i++) {
                if (i < NI) {
                    const unsigned int wv = idxS[(ps + 8 * i) * 64 + ch];
#pragma unroll
                    for (int j = 0; j < 4; j++) {
                        const unsigned int idx = (wv >> (8 * j)) & 255u;
                        const float4 lv = *(const float4*)(L + (((j << 4) + idx) << 8) + (og << 2));
                        acc[i].x = __fadd_rn(acc[i].x, lv.x);
                        acc[i].y = __fadd_rn(acc[i].y, lv.y);
                        acc[i].z = __fadd_rn(acc[i].z, lv.z);
                        acc[i].w = __fadd_rn(acc[i].w, lv.w);
                    }
                }
            }
        } else {
#pragma unroll
            for (int i = 0; i < 7; i++) {
                if (i < NI) {
                    const unsigned int wv = idxS[(ps + 8 * i) * 64 + ch];
#pragma unroll
                    for (int j = 0; j < 4; j++) {
                        const unsigned int idx = (wv >> (8 * j)) & 255u;
                        const float4 lv = *(const float4*)(L + (((j << 4) + idx) << 8) + (og << 2));
                        const bool foldB = fB[j] || (fC[j] && (int)idx >= Tt[j]);
                        if (foldB) {
                            tot[i].x = __fadd_rn(tot[i].x, acc[i].x); acc[i].x = lv.x;
                            tot[i].y = __fadd_rn(tot[i].y, acc[i].y); acc[i].y = lv.y;
                            tot[i].z = __fadd_rn(tot[i].z, acc[i].z); acc[i].z = lv.z;
                            tot[i].w = __fadd_rn(tot[i].w, acc[i].w); acc[i].w = lv.w;
                        } else {
                            acc[i].x = __fadd_rn(acc[i].x, lv.x);
                            acc[i].y = __fadd_rn(acc[i].y, lv.y);
                            acc[i].z = __fadd_rn(acc[i].z, lv.z);
                            acc[i].w = __fadd_rn(acc[i].w, lv.w);
                            if (fC[j]) {
                                tot[i].x = __fadd_rn(tot[i].x, acc[i].x); acc[i].x = 0.f;
                                tot[i].y = __fadd_rn(tot[i].y, acc[i].y); acc[i].y = 0.f;
                                tot[i].z = __fadd_rn(tot[i].z, acc[i].z); acc[i].z = 0.f;
                                tot[i].w = __fadd_rn(tot[i].w, acc[i].w); acc[i].w = 0.f;
                            }
                        }
                    }
                }
            }
        }
        __syncthreads();
        buf ^= 1;
    }
    const float4 sc4 = ((const float4*)scale)[og];
    const float4 bi4 = ((const float4*)bias)[og];
#pragma unroll
    for (int i = 0; i < 7; i++) {
        if (i < NI) {
            const int p = p0 + ps + 8 * i;
            float4 r; float s;
            s = __fadd_rn(tot[i].x, acc[i].x); r.x = fmaxf(__fadd_rn(__fmul_rn(s, sc4.x), bi4.x), 0.0f);
            s = __fadd_rn(tot[i].y, acc[i].y); r.y = fmaxf(__fadd_rn(__fmul_rn(s, sc4.y), bi4.y), 0.0f);
            s = __fadd_rn(tot[i].z, acc[i].z); r.z = fmaxf(__fadd_rn(__fmul_rn(s, sc4.z), bi4.z), 0.0f);
            s = __fadd_rn(tot[i].w, acc[i].w); r.w = fmaxf(__fadd_rn(__fmul_rn(s, sc4.w), bi4.w), 0.0f);
            *(float4*)(out + (b * PP + p) * 256 + (og << 2)) = r;
        }
    }
}

__global__ void __launch_bounds__(512, 1) k_accum_l1(const float* __restrict__ lut,
                                                     const float* __restrict__ scale,
                                                     const float* __restrict__ bias) {
    accum12_body(g_idx1, lut, scale, bias, g_out1);
}
__global__ void __launch_bounds__(512, 1) k_accum_l2(const float* __restrict__ lut,
                                                     const float* __restrict__ scale,
                                                     const float* __restrict__ bias) {
    accum12_body(g_idx2, lut, scale, bias, g_out2);
}

// ---------------- encode3 (unchanged, passing) ----------------
__global__ void __launch_bounds__(64) k_encode3(const float* __restrict__ cent) {
    const int b = blockIdx.y, h = blockIdx.x, cb = threadIdx.x;
    float c[16][4], c2[16];
#pragma unroll
    for (int k = 0; k < 16; k++) {
#pragma unroll
        for (int j = 0; j < 4; j++) c[k][j] = cent[(cb * 16 + k) * 4 + j];
        float s = __fmul_rn(c[k][0], c[k][0]);
        s = __fadd_rn(s, __fmul_rn(c[k][1], c[k][1]));
        s = __fadd_rn(s, __fmul_rn(c[k][2], c[k][2]));
        s = __fadd_rn(s, __fmul_rn(c[k][3], c[k][3]));
        c2[k] = s;
    }
    for (int w = 0; w < NH; w++) {
        const int p = h * NH + w;
        const float4 v = *(const float4*)&g_out2[(b * PP + p) * 256 + cb * 4];
        float best = 3.4e38f; int bi = 0;
#pragma unroll
        for (int k = 0; k < 16; k++) {
            float d = __fmaf_rn(v.x, c[k][0], 0.0f);
            d = __fmaf_rn(v.y, c[k][1], d);
            d = __fmaf_rn(v.z, c[k][2], d);
            d = __fmaf_rn(v.w, c[k][3], d);
            const float s = __fadd_rn(c2[k], -__fmul_rn(2.0f, d));
            if (s < best) { best = s; bi = k; }
        }
        ((unsigned char*)g_idx3)[(b * PP + p) * 64 + cb] = (unsigned char)bi;
    }
}

// ===================================================================
// accum3: flat sum, 512 threads = 128 og x 4 ps, p = ps + 4*i.
// grid (8, 32): pg = gx&3, oh = gx>>2. Chunk = 2 cb, dbuf.
// dyn smem = 2*65536 + 49*64 = 134208.
// ===================================================================
__global__ void __launch_bounds__(512, 1) k_accum3(const float* __restrict__ lut,
                                                   const float* __restrict__ scale,
                                                   const float* __restrict__ bias,
                                                   const float* __restrict__ xin,
                                                   float* __restrict__ out) {
    extern __shared__ float sm[];
    float* lutS = sm;
    unsigned char* idxB = (unsigned char*)(sm + 2 * 16384);
    const int b = blockIdx.y, gx = blockIdx.x, t = threadIdx.x;
    const int pg = gx & 3, oh = gx >> 2;
    const int og = t & 127, ps = t >> 7;
    const int p0 = pg * 49;
    const unsigned int* gi = (const unsigned int*)((const unsigned char*)g_idx3 + (b * PP + p0) * 64);
    for (int i = t; i < 49 * 16; i += 512) ((unsigned int*)idxB)[i] = gi[i];
    const int NI = (ps == 0) ? 13 : 12;
    float4 acc[13];
#pragma unroll
    for (int i = 0; i < 13; i++) acc[i] = make_float4(0.f, 0.f, 0.f, 0.f);
    const unsigned int sbase = (unsigned int)__cvta_generic_to_shared(lutS);
    const float4* gl = (const float4*)lut;
#pragma unroll
    for (int i = 0; i < 8; i++) {
        const int e4 = i * 512 + t;
        const int row = e4 >> 7, c4 = e4 & 127;
        cp16(sbase + e4 * 16, (const void*)(gl + row * 256 + oh * 128 + c4));
    }
    cpcommit();
    int buf = 0;
    for (int c2 = 0; c2 < 32; c2++) {
        if (c2 + 1 < 32) {
            const unsigned int d0 = sbase + (unsigned int)(buf ^ 1) * 65536u;
#pragma unroll
            for (int i = 0; i < 8; i++) {
                const int e4 = i * 512 + t;
                const int row = e4 >> 7, c4 = e4 & 127;
                cp16(d0 + e4 * 16, (const void*)(gl + ((c2 + 1) * 32 + row) * 256 + oh * 128 + c4));
            }
            cpcommit();
            cpwait1();
        } else {
            cpwait0();
        }
        __syncthreads();
        const float* L = lutS + buf * 16384;
#pragma unroll
        for (int i = 0; i < 13; i++) {
            if (i < NI) {
                const int p = ps + 4 * i;
                const unsigned char* ib = idxB + p * 64 + (c2 << 1);
#pragma unroll
                for (int j = 0; j < 2; j++) {
                    const unsigned int idx = ib[j];
                    const float4 lv = *(const float4*)(L + (((j << 4) + idx) << 9) + (og << 2));
                    acc[i].x = __fadd_rn(acc[i].x, lv.x);
                    acc[i].y = __fadd_rn(acc[i].y, lv.y);
                    acc[i].z = __fadd_rn(acc[i].z, lv.z);
                    acc[i].w = __fadd_rn(acc[i].w, lv.w);
                }
            }
        }
        __syncthreads();
        buf ^= 1;
    }
    float* tr = lutS;   // 512*49 floats
    __syncthreads();
#pragma unroll
    for (int i = 0; i < 13; i++) {
        if (i < NI) {
            const int p = ps + 4 * i;
            tr[(og * 4 + 0) * 49 + p] = acc[i].x;
            tr[(og * 4 + 1) * 49 + p] = acc[i].y;
            tr[(og * 4 + 2) * 49 + p] = acc[i].z;
            tr[(og * 4 + 3) * 49 + p] = acc[i].w;
        }
    }
    __syncthreads();
    {
        const int ol = t;
        const int O = oh * 512 + ol;
        const float scv = scale[O], biv = bias[O];
        const int base = (b * 1024 + O) * PP + p0;
        const float* trr = tr + ol * 49;
        for (int p = 0; p < 49; p++) {
            float r = __fadd_rn(__fadd_rn(__fmul_rn(trr[p], scv), biv), xin[base + p]);
            out[base + p] = fmaxf(r, 0.0f);
        }
    }
}

extern "C" void kernel_launch(void* const* d_in, const int* in_sizes, int n_in,
                              void* d_out, int out_size) {
    const float* x   = (const float*)d_in[0];
    const float* c1c = (const float*)d_in[1];
    const float* c1l = (const float*)d_in[2];
    const float* c1s = (const float*)d_in[3];
    const float* c1b = (const float*)d_in[4];
    const float* c2c = (const float*)d_in[5];
    const float* c2l = (const float*)d_in[6];
    const float* c2s = (const float*)d_in[7];
    const float* c2b = (const float*)d_in[8];
    const float* c3c = (const float*)d_in[9];
    const float* c3l = (const float*)d_in[10];
    const float* c3s = (const float*)d_in[11];
    const float* c3b = (const float*)d_in[12];
    float* out = (float*)d_out;

    cudaFuncSetAttribute(k_encode1,  cudaFuncAttributeMaxDynamicSharedMemorySize, 57344);
    cudaFuncSetAttribute(k_encode2,  cudaFuncAttributeMaxDynamicSharedMemorySize, 147456);
    cudaFuncSetAttribute(k_accum_l1, cudaFuncAttributeMaxDynamicSharedMemorySize, 143616);
    cudaFuncSetAttribute(k_accum_l2, cudaFuncAttributeMaxDynamicSharedMemorySize, 143616);
    cudaFuncSetAttribute(k_accum3,   cudaFuncAttributeMaxDynamicSharedMemorySize, 134208);

    k_encode1<<<dim3(NH, BB), 256, 57344>>>(x, c1c);
    k_accum_l1<<<dim3(4, BB), 512, 143616>>>(c1l, c1s, c1b);
    k_encode2<<<dim3(NH, BB), 256, 147456>>>(c2c);
    k_accum_l2<<<dim3(4, BB), 512, 143616>>>(c2l, c2s, c2b);
    k_encode3<<<dim3(NH, BB), 64>>>(c3c);
    k_accum3<<<dim3(8, BB), 512, 134208>>>(c3l, c3s, c3b, x, out);
    (void)in_sizes; (void)n_in; (void)out_size;
}